// round 15
// baseline (speedup 1.0000x reference)
#include <cuda_runtime.h>
#include <cuda_bf16.h>
#include <cstdint>

#define HH 64
#define WW 64
#define CIN 256
#define COUT 256
#define BB 8
#define KKT 9
#define HWSZ 4096
#define KTOT 2304

typedef unsigned long long ull;

// ---------------- scratch ----------------------------------------------------
__device__ float  g_xn[BB * HWSZ * CIN];
__device__ float  g_wB[KTOT * 32];
__device__ short4 g_sxy[BB * KKT * HWSZ];
__device__ float4 g_swt[BB * KKT * HWSZ];
__device__ __nv_bfloat16 g_wNh[COUT * KTOT];    // W hi [oc][k]
__device__ __nv_bfloat16 g_wNl[COUT * KTOT];    // W lo [oc][k]

// ---------------- helpers ----------------------------------------------------
__device__ __forceinline__ ull fma2(ull a, ull b, ull c) {
    ull d; asm("fma.rn.f32x2 %0, %1, %2, %3;" : "=l"(d) : "l"(a), "l"(b), "l"(c)); return d;
}
__device__ __forceinline__ float2 upk2(ull v) {
    float2 r; asm("mov.b64 {%0, %1}, %2;" : "=f"(r.x), "=f"(r.y) : "l"(v)); return r;
}
__device__ __forceinline__ ull dup2(float v) {
    ull r; asm("mov.b64 %0, {%1, %1};" : "=l"(r) : "f"(v)); return r;
}
__device__ __forceinline__ void cpa16(unsigned int s, const void* g) {
    asm volatile("cp.async.cg.shared.global [%0], [%1], 16;" :: "r"(s), "l"(g));
}
__device__ __forceinline__ uint32_t smem_u32(const void* p) {
    uint32_t a;
    asm("{ .reg .u64 t; cvta.to.shared.u64 t, %1; cvt.u32.u64 %0, t; }" : "=r"(a) : "l"(p));
    return a;
}
#define LDM4(d, a) \
    asm volatile("ldmatrix.sync.aligned.m8n8.x4.shared.b16 {%0,%1,%2,%3}, [%4];" \
                 : "=r"((d)[0]), "=r"((d)[1]), "=r"((d)[2]), "=r"((d)[3]) : "r"(a))
__device__ __forceinline__ void mma16816(float* c, const uint32_t* a,
                                         uint32_t b0, uint32_t b1) {
    asm volatile("mma.sync.aligned.m16n8k16.row.col.f32.bf16.bf16.f32 "
                 "{%0,%1,%2,%3}, {%4,%5,%6,%7}, {%8,%9}, {%0,%1,%2,%3};"
                 : "+f"(c[0]), "+f"(c[1]), "+f"(c[2]), "+f"(c[3])
                 : "r"(a[0]), "r"(a[1]), "r"(a[2]), "r"(a[3]), "r"(b0), "r"(b1));
}

// ---------------- k_transpose: NCHW -> NHWC --------------------------------
__global__ void k_transpose(const float* __restrict__ x) {
    __shared__ float tile[32][33];
    int b = blockIdx.z, p0 = blockIdx.x * 32, c0 = blockIdx.y * 32;
    const float* xb = x + (size_t)b * (CIN * HWSZ);
    float* ob = g_xn + (size_t)b * (HWSZ * CIN);
    int tx = threadIdx.x, ty = threadIdx.y;
#pragma unroll
    for (int i = 0; i < 4; i++)
        tile[ty + i * 8][tx] = xb[(size_t)(c0 + ty + i * 8) * HWSZ + p0 + tx];
    __syncthreads();
#pragma unroll
    for (int i = 0; i < 4; i++)
        ob[(size_t)(p0 + ty + i * 8) * CIN + c0 + tx] = tile[tx][ty + i * 8];
}

// ---------------- k_wN: reg_w -> hi/lo bf16 [oc][k] ------------------------
__global__ void k_wN(const float* __restrict__ reg_w) {
    int idx = blockIdx.x * 256 + threadIdx.x;
    if (idx >= COUT * KTOT) return;
    int oc = idx / KTOT, k = idx - oc * KTOT;
    int tap = k >> 8, c = k & 255;
    float w = reg_w[((size_t)oc * CIN + c) * KKT + tap];
    __nv_bfloat16 h = __float2bfloat16(w);
    g_wNh[idx] = h;
    g_wNl[idx] = __float2bfloat16(w - __bfloat162float(h));
}

// ---------------- k_wom: offset/mod weights [k][32] ------------------------
__global__ void k_wom(const float* __restrict__ ow, const float* __restrict__ mw) {
    int idx = blockIdx.x * 256 + threadIdx.x;
    if (idx >= KTOT * 32) return;
    int n = idx & 31, k = idx >> 5, tap = k >> 8, c = k & 255;
    float v = 0.f;
    if (n < 18)      v = ow[(size_t)(n * CIN + c) * KKT + tap];
    else if (n < 27) v = mw[(size_t)((n - 18) * CIN + c) * KKT + tap];
    g_wB[idx] = v;
}

// ---------------- k_offmod: offset/mod conv GEMM + prep (proven) -----------
__global__ void __launch_bounds__(128) k_offmod(const float* __restrict__ off_b,
                                                const float* __restrict__ mod_b) {
    __shared__ __align__(16) float As[32 * 64];
    __shared__ __align__(16) float Bs[32 * 32];
    __shared__ float red[64][28];
    int blk = blockIdx.x, b = blk >> 6, y = blk & 63, pos0 = y << 6;
    int tid = threadIdx.x, tx = tid & 7, ty = tid >> 3;
    int px = tid >> 2, cs2 = tid & 3, rB = tid >> 3, nB = (tid & 7) * 4;
    const float4* X4 = (const float4*)g_xn;

    ull acc[2][4];
#pragma unroll
    for (int i = 0; i < 2; i++)
#pragma unroll
        for (int j = 0; j < 4; j++) acc[i][j] = 0ULL;
    float4 ra[2][2], rb[2];

#define LOADSTAGE(s)                                                             \
    {                                                                            \
        int tap = (s) >> 3, cc = (s) & 7;                                        \
        int dy = tap / 3 - 1, dx = tap % 3 - 1;                                  \
        int y2 = y + dy;                                                         \
        bool rowok = (y2 >= 0) && (y2 < HH);                                     \
        _Pragma("unroll")                                                        \
        for (int it = 0; it < 2; it++) {                                         \
            int m = px + it * 32;                                                \
            int x2 = m + dx;                                                     \
            bool valid = rowok && (x2 >= 0) && (x2 < WW);                        \
            const float4* p = X4 + (size_t)(b * HWSZ + y2 * WW + x2) * 64        \
                                  + cc * 8 + cs2;                                \
            ra[it][0] = valid ? p[0] : make_float4(0.f, 0.f, 0.f, 0.f);          \
            ra[it][1] = valid ? p[4] : make_float4(0.f, 0.f, 0.f, 0.f);          \
        }                                                                        \
        rb[0] = *(const float4*)(g_wB + ((size_t)(s) * 32 + rB) * 32 + nB);      \
        rb[1] = *(const float4*)(g_wB + ((size_t)(s) * 32 + rB + 16) * 32 + nB); \
    }

    LOADSTAGE(0);
    for (int s = 0; s < 72; s++) {
        __syncthreads();
#pragma unroll
        for (int it = 0; it < 2; it++) {
            int col = (px + it * 32) ^ (cs2 << 3);
#pragma unroll
            for (int h = 0; h < 2; h++) {
                int kr = cs2 * 4 + h * 16;
                As[(kr + 0) * 64 + col] = (&ra[it][h].x)[0];
                As[(kr + 1) * 64 + col] = (&ra[it][h].x)[1];
                As[(kr + 2) * 64 + col] = (&ra[it][h].x)[2];
                As[(kr + 3) * 64 + col] = (&ra[it][h].x)[3];
            }
        }
        *(float4*)(Bs + rB * 32 + nB)        = rb[0];
        *(float4*)(Bs + (rB + 16) * 32 + nB) = rb[1];
        __syncthreads();
        if (s + 1 < 72) { LOADSTAGE(s + 1); }
#pragma unroll
        for (int kk = 0; kk < 32; kk++) {
            ulonglong2 a2 = *(const ulonglong2*)&As[kk * 64 + ((ty * 4) ^ ((kk & 12) << 1))];
            float4 bv = *(const float4*)&Bs[kk * 32 + tx * 4];
            ull bd[4] = {dup2(bv.x), dup2(bv.y), dup2(bv.z), dup2(bv.w)};
#pragma unroll
            for (int j = 0; j < 4; j++) {
                acc[0][j] = fma2(a2.x, bd[j], acc[0][j]);
                acc[1][j] = fma2(a2.y, bd[j], acc[1][j]);
            }
        }
    }
#undef LOADSTAGE

    __syncthreads();
#pragma unroll
    for (int i = 0; i < 2; i++)
#pragma unroll
        for (int j = 0; j < 4; j++) {
            int n = tx * 4 + j;
            if (n < 27) {
                float2 v = upk2(acc[i][j]);
                red[ty * 4 + 2 * i][n]     = v.x;
                red[ty * 4 + 2 * i + 1][n] = v.y;
            }
        }
    __syncthreads();

    for (int w = tid; w < 64 * 9; w += 128) {
        int px_i = w / 9, tap = w - px_i * 9, p2 = pos0 + px_i;
        float ay = red[px_i][2 * tap]     + off_b[2 * tap];
        float ax = red[px_i][2 * tap + 1] + off_b[2 * tap + 1];
        float am = red[px_i][18 + tap]    + mod_b[tap];
        float dyo = fminf(fmaxf(ay, -16.f), 16.f);
        float dxo = fminf(fmaxf(ax, -16.f), 16.f);
        float m = 1.f / (1.f + __expf(-am));
        float py  = dyo + (float)(tap / 3) + (float)y    - 1.f;
        float pxf = dxo + (float)(tap % 3) + (float)px_i - 1.f;
        float y0f = floorf(py), x0f = floorf(pxf);
        float ly = py - y0f, lx = pxf - x0f;
        int y0 = (int)y0f, x0 = (int)x0f;
        bool vy0 = (y0 >= 0) && (y0 < HH);
        bool vy1 = (y0 + 1 >= 0) && (y0 + 1 < HH);
        bool vx0 = (x0 >= 0) && (x0 < WW);
        bool vx1 = (x0 + 1 >= 0) && (x0 + 1 < WW);
        float w00 = (1.f - ly) * (1.f - lx) * m * ((vy0 && vx0) ? 1.f : 0.f);
        float w01 = (1.f - ly) * lx         * m * ((vy0 && vx1) ? 1.f : 0.f);
        float w10 = ly * (1.f - lx)         * m * ((vy1 && vx0) ? 1.f : 0.f);
        float w11 = ly * lx                 * m * ((vy1 && vx1) ? 1.f : 0.f);
        int y0c = min(max(y0, 0), HH - 1), y1c = min(max(y0 + 1, 0), HH - 1);
        int x0c = min(max(x0, 0), WW - 1), x1c = min(max(x0 + 1, 0), WW - 1);
        int si = (b * 9 + tap) * HWSZ + p2;
        g_sxy[si] = make_short4((short)y0c, (short)y1c, (short)x0c, (short)x1c);
        g_swt[si] = make_float4(w00, w01, w10, w11);
    }
}

// ---------------- k_main: fused gather + HMMA split-bf16 GEMM --------------
// grid (2, 256): x = oc half, y = (b, 128-px). K=2304 = 36 stages of 64.
// A tile (128px x 64c, hi/lo bf16) gathered IN-KERNEL from L2-resident g_xn
// (no im2col round-trip). A double-buffered, B hi/lo on 3-stage cp.async ring.
// smem rows padded to 144 B; 8 warps: 4 along M x 2 along N; 3-pass split.
#define RSTR 144
#define ATILE (128 * RSTR)            // 18432 bytes (one A or B matrix)
#define APAIR (2 * ATILE)             // 36864 (hi+lo)
#define BOFF  (2 * APAIR)             // 73728: start of B ring
#define SMEMT (BOFF + 3 * APAIR)      // 184320 total
__global__ void __launch_bounds__(256, 1) k_main(float* __restrict__ out) {
    extern __shared__ __align__(16) char smem[];
    uint32_t sb = smem_u32(smem);
    int tid = threadIdx.x, wid = tid >> 5, lid = tid & 31;
    int mb = blockIdx.y, b = mb >> 5, pos0 = (mb & 31) << 7;
    int noff = blockIdx.x << 7;
    int pb = b * HWSZ;
    const float4* X4 = (const float4*)g_xn;

    int r = tid >> 3, g = tid & 7;     // also gather: pxq = r, cs = g
    int wm = (wid >> 1) * 32, wn = (wid & 1) * 64;
    int lrow = (lid & 7) + ((lid >> 3) & 1) * 8;
    uint32_t lcol = ((lid >> 4) & 1) * 16;
    uint32_t aBase = (uint32_t)(wm + lrow) * RSTR + lcol;
    uint32_t bBase = (uint32_t)(wn + lrow) * RSTR + lcol;

    float acc[2][8][4];
#pragma unroll
    for (int i = 0; i < 2; i++)
#pragma unroll
        for (int j = 0; j < 8; j++)
#pragma unroll
            for (int q = 0; q < 4; q++) acc[i][j][q] = 0.f;

#define FILLB(s_)                                                                    \
    {                                                                                \
        uint32_t bb = sb + BOFF + ((s_) % 3) * APAIR;                                \
        _Pragma("unroll")                                                            \
        for (int q = 0; q < 4; q++) {                                                \
            int rr = r + 32 * q;                                                     \
            uint32_t d = bb + rr * RSTR + g * 16;                                    \
            cpa16(d,         g_wNh + (size_t)(noff + rr) * KTOT + (s_) * 64 + g * 8); \
            cpa16(d + ATILE, g_wNl + (size_t)(noff + rr) * KTOT + (s_) * 64 + g * 8); \
        }                                                                            \
        asm volatile("cp.async.commit_group;" ::: "memory");                         \
    }

#define GATHER(s_)                                                                   \
    {                                                                                \
        int tap = (s_) >> 2;                                                         \
        int c4b = ((s_) & 3) << 4;                                                   \
        char* abh = smem + ((s_) & 1) * APAIR;                                       \
        _Pragma("unroll")                                                            \
        for (int q = 0; q < 4; q++) {                                                \
            int px = r + 32 * q;                                                     \
            int si = (b * 9 + tap) * HWSZ + pos0 + px;                               \
            short4 sxy = g_sxy[si];                                                  \
            float4 wc = g_swt[si];                                                   \
            int a00 = (pb + sxy.x * WW + sxy.z) << 6;                                \
            int a01 = (pb + sxy.x * WW + sxy.w) << 6;                                \
            int a10 = (pb + sxy.y * WW + sxy.z) << 6;                                \
            int a11 = (pb + sxy.y * WW + sxy.w) << 6;                                \
            _Pragma("unroll")                                                        \
            for (int h = 0; h < 2; h++) {                                            \
                int c4 = c4b + g + 8 * h;                                            \
                float4 v0 = X4[a00 + c4];                                            \
                float4 v1 = X4[a01 + c4];                                            \
                float4 v2 = X4[a10 + c4];                                            \
                float4 v3 = X4[a11 + c4];                                            \
                float f0 = wc.x * v0.x + wc.y * v1.x + wc.z * v2.x + wc.w * v3.x;    \
                float f1 = wc.x * v0.y + wc.y * v1.y + wc.z * v2.y + wc.w * v3.y;    \
                float f2 = wc.x * v0.z + wc.y * v1.z + wc.z * v2.z + wc.w * v3.z;    \
                float f3 = wc.x * v0.w + wc.y * v1.w + wc.z * v2.w + wc.w * v3.w;    \
                __nv_bfloat16 h0 = __float2bfloat16(f0), h1 = __float2bfloat16(f1);  \
                __nv_bfloat16 h2 = __float2bfloat16(f2), h3 = __float2bfloat16(f3);  \
                __nv_bfloat162 th0 = __halves2bfloat162(h0, h1);                     \
                __nv_bfloat162 th1 = __halves2bfloat162(h2, h3);                     \
                __nv_bfloat162 tl0 = __halves2bfloat162(                             \
                    __float2bfloat16(f0 - __bfloat162float(h0)),                     \
                    __float2bfloat16(f1 - __bfloat162float(h1)));                    \
                __nv_bfloat162 tl1 = __halves2bfloat162(                             \
                    __float2bfloat16(f2 - __bfloat162float(h2)),                     \
                    __float2bfloat16(f3 - __bfloat162float(h3)));                    \
                uint2 uh, ulv;                                                       \
                uh.x = *(unsigned*)&th0;  uh.y = *(unsigned*)&th1;                   \
                ulv.x = *(unsigned*)&tl0; ulv.y = *(unsigned*)&tl1;                  \
                int off = px * RSTR + (g + 8 * h) * 8;                               \
                *(uint2*)(abh + off)         = uh;                                   \
                *(uint2*)(abh + off + ATILE) = ulv;                                  \
            }                                                                        \
        }                                                                            \
    }

    FILLB(0);
    FILLB(1);
    GATHER(0);

    for (int s = 0; s < 36; s++) {
        if (s + 2 < 36) { FILLB(s + 2); }
        else { asm volatile("cp.async.commit_group;" ::: "memory"); }
        asm volatile("cp.async.wait_group 2;" ::: "memory");
        __syncthreads();

        if (s + 1 < 36) { GATHER(s + 1); }   // LDGs overlap the MMAs below

        uint32_t bufA  = sb + (s & 1) * APAIR;
        uint32_t bufAl = bufA + ATILE;
        uint32_t bufB  = sb + BOFF + (s % 3) * APAIR;
        uint32_t bufBl = bufB + ATILE;
#pragma unroll
        for (int ks = 0; ks < 4; ks++) {
            uint32_t ko = ks * 32;
            uint32_t ah[2][4], al[2][4], bh[4][4], bl[4][4];
#pragma unroll
            for (int mt = 0; mt < 2; mt++) {
                LDM4(ah[mt], bufA  + aBase + mt * (16 * RSTR) + ko);
                LDM4(al[mt], bufAl + aBase + mt * (16 * RSTR) + ko);
            }
#pragma unroll
            for (int nt = 0; nt < 4; nt++) {
                LDM4(bh[nt], bufB  + bBase + nt * (16 * RSTR) + ko);
                LDM4(bl[nt], bufBl + bBase + nt * (16 * RSTR) + ko);
            }
#pragma unroll
            for (int mt = 0; mt < 2; mt++)
#pragma unroll
                for (int n8 = 0; n8 < 8; n8++) {
                    int nt = n8 >> 1, h = n8 & 1;
                    mma16816(acc[mt][n8], ah[mt], bh[nt][h], bh[nt][h + 2]);
                    mma16816(acc[mt][n8], ah[mt], bl[nt][h], bl[nt][h + 2]);
                    mma16816(acc[mt][n8], al[mt], bh[nt][h], bh[nt][h + 2]);
                }
        }
        __syncthreads();
    }
#undef FILLB
#undef GATHER

    // epilogue: c0:(m,n) c1:(m,n+1) c2:(m+8,n) c3:(m+8,n+1)
    int mrow = lid >> 2, ncol = (lid & 3) * 2;
#pragma unroll
    for (int mt = 0; mt < 2; mt++)
#pragma unroll
        for (int n8 = 0; n8 < 8; n8++) {
            int m = pos0 + wm + mt * 16 + mrow;
            int n = noff + wn + n8 * 8 + ncol;
            float* o0 = out + (size_t)(b * COUT + n) * HWSZ + m;
            float* o1 = o0 + HWSZ;
            o0[0] = acc[mt][n8][0];
            o1[0] = acc[mt][n8][1];
            o0[8] = acc[mt][n8][2];
            o1[8] = acc[mt][n8][3];
        }
}

// ---------------- launch ----------------------------------------------------
extern "C" void kernel_launch(void* const* d_in, const int* in_sizes, int n_in,
                              void* d_out, int out_size) {
    const float* x        = (const float*)d_in[0];
    const float* offset_w = (const float*)d_in[1];
    const float* offset_b = (const float*)d_in[2];
    const float* mod_w    = (const float*)d_in[3];
    const float* mod_b    = (const float*)d_in[4];
    const float* reg_w    = (const float*)d_in[5];
    float* out = (float*)d_out;

    cudaFuncSetAttribute(k_main, cudaFuncAttributeMaxDynamicSharedMemorySize, SMEMT);

    k_transpose<<<dim3(128, 8, 8), dim3(32, 8)>>>(x);
    k_wN<<<(COUT * KTOT + 255) / 256, 256>>>(reg_w);
    k_wom<<<(KTOT * 32 + 255) / 256, 256>>>(offset_w, mod_w);
    k_offmod<<<512, 128>>>(offset_b, mod_b);
    k_main<<<dim3(2, 256), 256, SMEMT>>>(out);
}

// round 16
// speedup vs baseline: 1.1798x; 1.1798x over previous
#include <cuda_runtime.h>
#include <cuda_bf16.h>
#include <cstdint>

#define HH 64
#define WW 64
#define CIN 256
#define COUT 256
#define BB 8
#define KKT 9
#define HWSZ 4096
#define KTOT 2304

typedef unsigned long long ull;

// ---------------- scratch ----------------------------------------------------
__device__ float  g_xn[BB * HWSZ * CIN];
__device__ __nv_bfloat16 g_xh[BB * HWSZ * CIN];   // x hi (NHWC)
__device__ __nv_bfloat16 g_xl[BB * HWSZ * CIN];   // x lo
__device__ short4 g_sxy[BB * KKT * HWSZ];
__device__ float4 g_swt[BB * KKT * HWSZ];
__device__ __nv_bfloat16 g_Ah[(size_t)BB * KKT * HWSZ * CIN];   // im2col hi
__device__ __nv_bfloat16 g_Al[(size_t)BB * KKT * HWSZ * CIN];   // im2col lo
__device__ __nv_bfloat16 g_wNh[COUT * KTOT];      // main W hi [oc][k]
__device__ __nv_bfloat16 g_wNl[COUT * KTOT];      // main W lo
__device__ __nv_bfloat16 g_wOh[32 * KTOT];        // off/mod W hi [n][k]
__device__ __nv_bfloat16 g_wOl[32 * KTOT];        // off/mod W lo

// ---------------- helpers ----------------------------------------------------
__device__ __forceinline__ void cpa16(unsigned int s, const void* g) {
    asm volatile("cp.async.cg.shared.global [%0], [%1], 16;" :: "r"(s), "l"(g));
}
__device__ __forceinline__ void cpa16z(unsigned int s, const void* g, unsigned int sz) {
    asm volatile("cp.async.cg.shared.global [%0], [%1], 16, %2;" :: "r"(s), "l"(g), "r"(sz));
}
__device__ __forceinline__ uint32_t smem_u32(const void* p) {
    uint32_t a;
    asm("{ .reg .u64 t; cvta.to.shared.u64 t, %1; cvt.u32.u64 %0, t; }" : "=r"(a) : "l"(p));
    return a;
}
#define LDM4(d, a) \
    asm volatile("ldmatrix.sync.aligned.m8n8.x4.shared.b16 {%0,%1,%2,%3}, [%4];" \
                 : "=r"((d)[0]), "=r"((d)[1]), "=r"((d)[2]), "=r"((d)[3]) : "r"(a))
__device__ __forceinline__ void mma16816(float* c, const uint32_t* a,
                                         uint32_t b0, uint32_t b1) {
    asm volatile("mma.sync.aligned.m16n8k16.row.col.f32.bf16.bf16.f32 "
                 "{%0,%1,%2,%3}, {%4,%5,%6,%7}, {%8,%9}, {%0,%1,%2,%3};"
                 : "+f"(c[0]), "+f"(c[1]), "+f"(c[2]), "+f"(c[3])
                 : "r"(a[0]), "r"(a[1]), "r"(a[2]), "r"(a[3]), "r"(b0), "r"(b1));
}

// ---------------- k_transpose: NCHW -> NHWC fp32 + bf16 hi/lo --------------
__global__ void k_transpose(const float* __restrict__ x) {
    __shared__ float tile[32][33];
    int b = blockIdx.z, p0 = blockIdx.x * 32, c0 = blockIdx.y * 32;
    const float* xb = x + (size_t)b * (CIN * HWSZ);
    size_t ob = (size_t)b * (HWSZ * CIN);
    int tx = threadIdx.x, ty = threadIdx.y;
#pragma unroll
    for (int i = 0; i < 4; i++)
        tile[ty + i * 8][tx] = xb[(size_t)(c0 + ty + i * 8) * HWSZ + p0 + tx];
    __syncthreads();
#pragma unroll
    for (int i = 0; i < 4; i++) {
        float v = tile[tx][ty + i * 8];
        size_t idx = ob + (size_t)(p0 + ty + i * 8) * CIN + c0 + tx;
        g_xn[idx] = v;
        __nv_bfloat16 h = __float2bfloat16(v);
        g_xh[idx] = h;
        g_xl[idx] = __float2bfloat16(v - __bfloat162float(h));
    }
}

// ---------------- k_wN: reg_w -> hi/lo bf16 [oc][k] ------------------------
__global__ void k_wN(const float* __restrict__ reg_w) {
    int idx = blockIdx.x * 256 + threadIdx.x;
    if (idx >= COUT * KTOT) return;
    int oc = idx / KTOT, k = idx - oc * KTOT;
    int tap = k >> 8, c = k & 255;
    float w = reg_w[((size_t)oc * CIN + c) * KKT + tap];
    __nv_bfloat16 h = __float2bfloat16(w);
    g_wNh[idx] = h;
    g_wNl[idx] = __float2bfloat16(w - __bfloat162float(h));
}

// ---------------- k_wO: offset/mod weights -> hi/lo bf16 [32][k] -----------
__global__ void k_wO(const float* __restrict__ ow, const float* __restrict__ mw) {
    int idx = blockIdx.x * 256 + threadIdx.x;
    if (idx >= 32 * KTOT) return;
    int n = idx / KTOT, k = idx - n * KTOT;
    int tap = k >> 8, c = k & 255;
    float v = 0.f;
    if (n < 18)      v = ow[(size_t)(n * CIN + c) * KKT + tap];
    else if (n < 27) v = mw[(size_t)((n - 18) * CIN + c) * KKT + tap];
    __nv_bfloat16 h = __float2bfloat16(v);
    g_wOh[idx] = h;
    g_wOl[idx] = __float2bfloat16(v - __bfloat162float(h));
}

// ---------------- k_offmod: HMMA split-bf16 GEMM + sampling prep -----------
// grid 512 = (b, image row). M=64 px, N=32 (27 used), K=2304 = 36 stages x64.
// 128 thr, 4 warps each 16 m-rows x full N. 3-stage cp.async ring; A rows
// zero-filled for OOB via cp.async src-size=0.
#define ORSTR 144
#define OATL (64 * ORSTR)             // 9216: one A matrix
#define OBTL (32 * ORSTR)             // 4608: one B matrix
#define OSTG (2 * OATL + 2 * OBTL)    // 27648 per stage
#define ORED (3 * OSTG)               // 82944: red offset
#define OSMT (ORED + 64 * 28 * 4)     // 90112 total
__global__ void __launch_bounds__(128) k_offmod(const float* __restrict__ off_b,
                                                const float* __restrict__ mod_b) {
    extern __shared__ __align__(16) char smem[];
    uint32_t sb = smem_u32(smem);
    float* red = (float*)(smem + ORED);
    int tid = threadIdx.x, wid = tid >> 5, lid = tid & 31;
    int blk = blockIdx.x, b = blk >> 6, y = blk & 63, pos0 = y << 6;
    int r = tid >> 3, g = tid & 7;
    int wm = wid * 16;
    int lrow = (lid & 7) + ((lid >> 3) & 1) * 8;
    uint32_t lcol = ((lid >> 4) & 1) * 16;
    uint32_t aBase = (uint32_t)(wm + lrow) * ORSTR + lcol;
    uint32_t bBase = (uint32_t)lrow * ORSTR + lcol;

    float acc[4][4];
#pragma unroll
    for (int j = 0; j < 4; j++)
#pragma unroll
        for (int q = 0; q < 4; q++) acc[j][q] = 0.f;

#define FILLO(s_)                                                                    \
    {                                                                                \
        uint32_t bb = sb + ((s_) % 3) * OSTG;                                        \
        int tap = (s_) >> 2;                                                         \
        int c0 = ((s_) & 3) << 6;                                                    \
        int dy = tap / 3 - 1, dx = tap % 3 - 1;                                      \
        int y2 = y + dy;                                                             \
        bool rowok = (y2 >= 0) && (y2 < HH);                                         \
        int y2c = min(max(y2, 0), HH - 1);                                           \
        _Pragma("unroll")                                                            \
        for (int q = 0; q < 4; q++) {                                                \
            int rr = r + 16 * q;                                                     \
            int x2 = rr + dx;                                                        \
            unsigned int sz = (rowok && x2 >= 0 && x2 < WW) ? 16u : 0u;              \
            int x2c = min(max(x2, 0), WW - 1);                                       \
            size_t idx = ((size_t)(b * HWSZ + y2c * WW + x2c)) * CIN + c0 + g * 8;   \
            uint32_t d = bb + rr * ORSTR + g * 16;                                   \
            cpa16z(d,        g_xh + idx, sz);                                        \
            cpa16z(d + OATL, g_xl + idx, sz);                                        \
        }                                                                            \
        _Pragma("unroll")                                                            \
        for (int p2 = 0; p2 < 2; p2++) {                                             \
            int rr = r + 16 * p2;                                                    \
            uint32_t d = bb + 2 * OATL + rr * ORSTR + g * 16;                        \
            cpa16(d,        g_wOh + (size_t)rr * KTOT + (s_) * 64 + g * 8);          \
            cpa16(d + OBTL, g_wOl + (size_t)rr * KTOT + (s_) * 64 + g * 8);          \
        }                                                                            \
        asm volatile("cp.async.commit_group;" ::: "memory");                         \
    }

    FILLO(0);
    FILLO(1);
    for (int s = 0; s < 36; s++) {
        if (s + 2 < 36) { FILLO(s + 2); }
        else { asm volatile("cp.async.commit_group;" ::: "memory"); }
        asm volatile("cp.async.wait_group 2;" ::: "memory");
        __syncthreads();

        uint32_t bufA  = sb + (s % 3) * OSTG;
        uint32_t bufAl = bufA + OATL;
        uint32_t bufB  = bufA + 2 * OATL;
        uint32_t bufBl = bufB + OBTL;
#pragma unroll
        for (int ks = 0; ks < 4; ks++) {
            uint32_t ko = ks * 32;
            uint32_t ah[4], al[4], bh[2][4], bl[2][4];
            LDM4(ah, bufA  + aBase + ko);
            LDM4(al, bufAl + aBase + ko);
#pragma unroll
            for (int nt = 0; nt < 2; nt++) {
                LDM4(bh[nt], bufB  + bBase + nt * (16 * ORSTR) + ko);
                LDM4(bl[nt], bufBl + bBase + nt * (16 * ORSTR) + ko);
            }
#pragma unroll
            for (int n8 = 0; n8 < 4; n8++) {
                int nt = n8 >> 1, h = n8 & 1;
                mma16816(acc[n8], ah, bh[nt][h], bh[nt][h + 2]);
                mma16816(acc[n8], ah, bl[nt][h], bl[nt][h + 2]);
                mma16816(acc[n8], al, bh[nt][h], bh[nt][h + 2]);
            }
        }
        __syncthreads();
    }
#undef FILLO

    // accs -> red[m][n]
    int mrow = lid >> 2, ncol = (lid & 3) * 2;
#pragma unroll
    for (int n8 = 0; n8 < 4; n8++) {
        int n = n8 * 8 + ncol;
        int m0 = wm + mrow, m1 = wm + mrow + 8;
        if (n < 27) {
            red[m0 * 28 + n] = acc[n8][0];
            red[m1 * 28 + n] = acc[n8][2];
        }
        if (n + 1 < 27) {
            red[m0 * 28 + n + 1] = acc[n8][1];
            red[m1 * 28 + n + 1] = acc[n8][3];
        }
    }
    __syncthreads();

    // prep: 576 (px, tap) items
    for (int w = tid; w < 64 * 9; w += 128) {
        int px_i = w / 9, tap = w - px_i * 9, p2 = pos0 + px_i;
        float ay = red[px_i * 28 + 2 * tap]     + off_b[2 * tap];
        float ax = red[px_i * 28 + 2 * tap + 1] + off_b[2 * tap + 1];
        float am = red[px_i * 28 + 18 + tap]    + mod_b[tap];
        float dyo = fminf(fmaxf(ay, -16.f), 16.f);
        float dxo = fminf(fmaxf(ax, -16.f), 16.f);
        float m = 1.f / (1.f + __expf(-am));
        float py  = dyo + (float)(tap / 3) + (float)y    - 1.f;
        float pxf = dxo + (float)(tap % 3) + (float)px_i - 1.f;
        float y0f = floorf(py), x0f = floorf(pxf);
        float ly = py - y0f, lx = pxf - x0f;
        int y0 = (int)y0f, x0 = (int)x0f;
        bool vy0 = (y0 >= 0) && (y0 < HH);
        bool vy1 = (y0 + 1 >= 0) && (y0 + 1 < HH);
        bool vx0 = (x0 >= 0) && (x0 < WW);
        bool vx1 = (x0 + 1 >= 0) && (x0 + 1 < WW);
        float w00 = (1.f - ly) * (1.f - lx) * m * ((vy0 && vx0) ? 1.f : 0.f);
        float w01 = (1.f - ly) * lx         * m * ((vy0 && vx1) ? 1.f : 0.f);
        float w10 = ly * (1.f - lx)         * m * ((vy1 && vx0) ? 1.f : 0.f);
        float w11 = ly * lx                 * m * ((vy1 && vx1) ? 1.f : 0.f);
        int y0c = min(max(y0, 0), HH - 1), y1c = min(max(y0 + 1, 0), HH - 1);
        int x0c = min(max(x0, 0), WW - 1), x1c = min(max(x0 + 1, 0), WW - 1);
        int si = (b * 9 + tap) * HWSZ + p2;
        g_sxy[si] = make_short4((short)y0c, (short)y1c, (short)x0c, (short)x1c);
        g_swt[si] = make_float4(w00, w01, w10, w11);
    }
}

// ---------------- k_gather: bilinear -> hi/lo bf16 im2col (R14, proven) ----
__global__ void __launch_bounds__(256) k_gather() {
    int blk = blockIdx.x, b = blk >> 7, p32 = blk & 127, pos0 = p32 << 5;
    int tid = threadIdx.x, px = tid >> 3, cs = tid & 7;
    int pb = b * HWSZ;
    const float4* X4 = (const float4*)g_xn;

    for (int tap = 0; tap < 9; tap++) {
        int bt = b * 9 + tap;
        int si = bt * HWSZ + pos0 + px;
        short4 s = g_sxy[si];
        float4 wc = g_swt[si];
        int a00 = (pb + s.x * WW + s.z) << 6;
        int a01 = (pb + s.x * WW + s.w) << 6;
        int a10 = (pb + s.y * WW + s.z) << 6;
        int a11 = (pb + s.y * WW + s.w) << 6;
        size_t rowb = ((size_t)bt * HWSZ + pos0 + px) * 256;

#pragma unroll
        for (int i = 0; i < 8; i++) {
            int c4 = i * 8 + cs;
            float4 v0 = X4[a00 + c4];
            float4 v1 = X4[a01 + c4];
            float4 v2 = X4[a10 + c4];
            float4 v3 = X4[a11 + c4];
            float f0 = wc.x * v0.x + wc.y * v1.x + wc.z * v2.x + wc.w * v3.x;
            float f1 = wc.x * v0.y + wc.y * v1.y + wc.z * v2.y + wc.w * v3.y;
            float f2 = wc.x * v0.z + wc.y * v1.z + wc.z * v2.z + wc.w * v3.z;
            float f3 = wc.x * v0.w + wc.y * v1.w + wc.z * v2.w + wc.w * v3.w;
            __nv_bfloat16 h0 = __float2bfloat16(f0), h1 = __float2bfloat16(f1);
            __nv_bfloat16 h2 = __float2bfloat16(f2), h3 = __float2bfloat16(f3);
            __nv_bfloat162 th0 = __halves2bfloat162(h0, h1);
            __nv_bfloat162 th1 = __halves2bfloat162(h2, h3);
            __nv_bfloat162 tl0 = __halves2bfloat162(
                __float2bfloat16(f0 - __bfloat162float(h0)),
                __float2bfloat16(f1 - __bfloat162float(h1)));
            __nv_bfloat162 tl1 = __halves2bfloat162(
                __float2bfloat16(f2 - __bfloat162float(h2)),
                __float2bfloat16(f3 - __bfloat162float(h3)));
            uint2 uh, ulv;
            uh.x = *(unsigned*)&th0;  uh.y = *(unsigned*)&th1;
            ulv.x = *(unsigned*)&tl0; ulv.y = *(unsigned*)&tl1;
            *(uint2*)(g_Ah + rowb + c4 * 4) = uh;
            *(uint2*)(g_Al + rowb + c4 * 4) = ulv;
        }
    }
}

// ---------------- k_main: HMMA split-bf16 GEMM (R14, proven) ---------------
// grid (2, 256): x = oc half (paired blocks share A in L2), y = (b, 128-px).
// K=2304 = 36 stages of 64, 3-stage cp.async ring (216 KB).
#define RSTR 144
#define ATILE (128 * RSTR)
#define BUFSZ (4 * ATILE)
#define NSTG 3
__global__ void __launch_bounds__(256, 1) k_main(float* __restrict__ out) {
    extern __shared__ __align__(16) char smem[];
    uint32_t sb = smem_u32(smem);
    int tid = threadIdx.x, wid = tid >> 5, lid = tid & 31;
    int mb = blockIdx.y, b = mb >> 5, pos0 = (mb & 31) << 7;
    int noff = blockIdx.x << 7;

    int r = tid >> 3, g = tid & 7;
    int wm = (wid >> 1) * 32, wn = (wid & 1) * 64;
    int lrow = (lid & 7) + ((lid >> 3) & 1) * 8;
    uint32_t lcol = ((lid >> 4) & 1) * 16;
    uint32_t aBase = (uint32_t)(wm + lrow) * RSTR + lcol;
    uint32_t bBase = (uint32_t)(wn + lrow) * RSTR + lcol;

    float acc[2][8][4];
#pragma unroll
    for (int i = 0; i < 2; i++)
#pragma unroll
        for (int j = 0; j < 8; j++)
#pragma unroll
            for (int q = 0; q < 4; q++) acc[i][j][q] = 0.f;

#define FILLST(s_)                                                                   \
    {                                                                                \
        uint32_t bb = sb + ((s_) % NSTG) * BUFSZ;                                    \
        int tap = (s_) >> 2;                                                         \
        int c0 = ((s_) & 3) << 6;                                                    \
        size_t arow = (size_t)(b * 9 + tap) * HWSZ + pos0;                           \
        _Pragma("unroll")                                                            \
        for (int q = 0; q < 4; q++) {                                                \
            int rr = r + 32 * q;                                                     \
            uint32_t d = bb + rr * RSTR + g * 16;                                    \
            cpa16(d,             g_Ah + (arow + rr) * 256 + c0 + g * 8);             \
            cpa16(d + ATILE,     g_Al + (arow + rr) * 256 + c0 + g * 8);             \
            cpa16(d + 2 * ATILE, g_wNh + (size_t)(noff + rr) * KTOT + (s_) * 64 + g * 8); \
            cpa16(d + 3 * ATILE, g_wNl + (size_t)(noff + rr) * KTOT + (s_) * 64 + g * 8); \
        }                                                                            \
        asm volatile("cp.async.commit_group;" ::: "memory");                         \
    }

    FILLST(0);
    FILLST(1);
    for (int s = 0; s < 36; s++) {
        if (s + 2 < 36) { FILLST(s + 2); }
        else { asm volatile("cp.async.commit_group;" ::: "memory"); }
        asm volatile("cp.async.wait_group 2;" ::: "memory");
        __syncthreads();

        uint32_t bufA  = sb + (s % NSTG) * BUFSZ;
        uint32_t bufAl = bufA + ATILE;
        uint32_t bufB  = bufA + 2 * ATILE;
        uint32_t bufBl = bufA + 3 * ATILE;
#pragma unroll
        for (int ks = 0; ks < 4; ks++) {
            uint32_t ko = ks * 32;
            uint32_t ah[2][4], al[2][4], bh[4][4], bl[4][4];
#pragma unroll
            for (int mt = 0; mt < 2; mt++) {
                LDM4(ah[mt], bufA  + aBase + mt * (16 * RSTR) + ko);
                LDM4(al[mt], bufAl + aBase + mt * (16 * RSTR) + ko);
            }
#pragma unroll
            for (int nt = 0; nt < 4; nt++) {
                LDM4(bh[nt], bufB  + bBase + nt * (16 * RSTR) + ko);
                LDM4(bl[nt], bufBl + bBase + nt * (16 * RSTR) + ko);
            }
#pragma unroll
            for (int mt = 0; mt < 2; mt++)
#pragma unroll
                for (int n8 = 0; n8 < 8; n8++) {
                    int nt = n8 >> 1, h = n8 & 1;
                    mma16816(acc[mt][n8], ah[mt], bh[nt][h], bh[nt][h + 2]);
                    mma16816(acc[mt][n8], ah[mt], bl[nt][h], bl[nt][h + 2]);
                    mma16816(acc[mt][n8], al[mt], bh[nt][h], bh[nt][h + 2]);
                }
        }
        __syncthreads();
    }
#undef FILLST

    int mrow = lid >> 2, ncol = (lid & 3) * 2;
#pragma unroll
    for (int mt = 0; mt < 2; mt++)
#pragma unroll
        for (int n8 = 0; n8 < 8; n8++) {
            int m = pos0 + wm + mt * 16 + mrow;
            int n = noff + wn + n8 * 8 + ncol;
            float* o0 = out + (size_t)(b * COUT + n) * HWSZ + m;
            float* o1 = o0 + HWSZ;
            o0[0] = acc[mt][n8][0];
            o1[0] = acc[mt][n8][1];
            o0[8] = acc[mt][n8][2];
            o1[8] = acc[mt][n8][3];
        }
}

// ---------------- launch ----------------------------------------------------
extern "C" void kernel_launch(void* const* d_in, const int* in_sizes, int n_in,
                              void* d_out, int out_size) {
    const float* x        = (const float*)d_in[0];
    const float* offset_w = (const float*)d_in[1];
    const float* offset_b = (const float*)d_in[2];
    const float* mod_w    = (const float*)d_in[3];
    const float* mod_b    = (const float*)d_in[4];
    const float* reg_w    = (const float*)d_in[5];
    float* out = (float*)d_out;

    cudaFuncSetAttribute(k_main, cudaFuncAttributeMaxDynamicSharedMemorySize,
                         NSTG * BUFSZ);
    cudaFuncSetAttribute(k_offmod, cudaFuncAttributeMaxDynamicSharedMemorySize, OSMT);

    k_transpose<<<dim3(128, 8, 8), dim3(32, 8)>>>(x);
    k_wN<<<(COUT * KTOT + 255) / 256, 256>>>(reg_w);
    k_wO<<<(32 * KTOT + 255) / 256, 256>>>(offset_w, mod_w);
    k_offmod<<<512, 128, OSMT>>>(offset_b, mod_b);
    k_gather<<<1024, 256>>>();
    k_main<<<dim3(2, 256), 256, NSTG * BUFSZ>>>(out);
}